// round 2
// baseline (speedup 1.0000x reference)
#include <cuda_runtime.h>
#include <stdint.h>

// BloomEmbedding: out[n, h*32 + j] = tables[h, hash(ids[n], 42+h), j]
// ids: [819200] int32, tables: [4, 1000000, 32] f32, out: [819200, 128] f32
//
// R2: cache-policy tuning for the L2 reuse window.
//   - output stores use __stcs (evict-first): 419 MB of write data never
//     re-read; keep it from evicting table lines in L2.
//   - table gathers use __ldcg (L2-only): L1 is useless for a 286 MB random
//     working set; avoid L1 allocate/replay overhead.

#define TABLE_SIZE 1000000u
#define SEED 42u

__device__ __forceinline__ uint32_t hash_id(uint32_t id, uint32_t seed) {
    uint32_t x = id + seed;
    x ^= x >> 16;
    x *= 0x7FEB352Du;
    x ^= x >> 15;
    x *= 0x846CA68Bu;
    x ^= x >> 16;
    return x % TABLE_SIZE;
}

__global__ void __launch_bounds__(256)
bloom_embedding_kernel(const int* __restrict__ ids,
                       const float4* __restrict__ tables,
                       float4* __restrict__ out,
                       int n_ids) {
    int t = blockIdx.x * blockDim.x + threadIdx.x;
    int total = n_ids * 32;              // one float4 per thread
    if (t >= total) return;

    int n    = t >> 5;                   // id index
    int lane = t & 31;                   // 0..31 within the 128-float row
    int h    = lane >> 3;                // hash table 0..3
    int j    = lane & 7;                 // float4 within the 32-float sub-row

    uint32_t id  = (uint32_t)__ldg(ids + n);
    uint32_t idx = hash_id(id, SEED + (uint32_t)h);

    // tables laid out as [H][TABLE_SIZE][32 floats] = [H][TABLE_SIZE][8 float4]
    size_t src = ((size_t)h * TABLE_SIZE + idx) * 8u + (size_t)j;
    float4 v = __ldcg(tables + src);     // L2-only: keep table lines in L2

    // out row n is 128 floats = 32 float4; lane == h*8 + j
    __stcs(out + (size_t)n * 32u + (size_t)lane, v);  // evict-first: don't pollute L2
}

extern "C" void kernel_launch(void* const* d_in, const int* in_sizes, int n_in,
                              void* d_out, int out_size) {
    const int*    ids    = (const int*)d_in[0];
    const float4* tables = (const float4*)d_in[1];
    float4*       out    = (float4*)d_out;

    int n_ids = in_sizes[0];             // 819200
    int total = n_ids * 32;
    int threads = 256;
    int blocks = (total + threads - 1) / threads;
    bloom_embedding_kernel<<<blocks, threads>>>(ids, tables, out, n_ids);
}

// round 3
// speedup vs baseline: 1.3552x; 1.3552x over previous
#include <cuda_runtime.h>
#include <stdint.h>

// BloomEmbedding: out[n, h*32 + j] = tables[h, hash(ids[n], 42+h), j]
// ids: [819200] int32, tables: [4, 1000000, 32] f32, out: [819200, 128] f32
//
// R3: MLP. One gather per thread left the SM with only ~6KB of reads in
// flight (latency-bound at ~10.6 B/cyc/SM by Little's law). Each thread now
// handles IDS_PER_THREAD=4 consecutive ids for its lane role -> 4 independent
// front-batched LDG.128s per thread.

#define TABLE_SIZE 1000000u
#define SEED 42u
#define IDS_PER_THREAD 4

__device__ __forceinline__ uint32_t hash_id(uint32_t id, uint32_t seed) {
    uint32_t x = id + seed;
    x ^= x >> 16;
    x *= 0x7FEB352Du;
    x ^= x >> 15;
    x *= 0x846CA68Bu;
    x ^= x >> 16;
    return x % TABLE_SIZE;
}

__global__ void __launch_bounds__(256)
bloom_embedding_kernel(const int* __restrict__ ids,
                       const float4* __restrict__ tables,
                       float4* __restrict__ out,
                       int n_ids) {
    int t = blockIdx.x * blockDim.x + threadIdx.x;
    int lane = t & 31;                   // 0..31 within the 128-float row
    int h    = lane >> 3;                // hash table 0..3
    int j    = lane & 7;                 // float4 within the 32-float sub-row
    uint32_t seed = SEED + (uint32_t)h;

    int n0 = (t >> 5) * IDS_PER_THREAD;  // first id of this group
    if (n0 >= n_ids) return;

    // n_ids = 819200 is divisible by 4, and grid is sized exactly, so the
    // full unroll is always in-bounds; keep a guard for generality.
    if (n0 + IDS_PER_THREAD <= n_ids) {
        uint32_t idn[IDS_PER_THREAD];
        size_t   src[IDS_PER_THREAD];
        #pragma unroll
        for (int k = 0; k < IDS_PER_THREAD; k++) {
            idn[k] = (uint32_t)__ldg(ids + n0 + k);
            uint32_t idx = hash_id(idn[k], seed);
            src[k] = ((size_t)h * TABLE_SIZE + idx) * 8u + (size_t)j;
        }
        float4 v[IDS_PER_THREAD];
        #pragma unroll
        for (int k = 0; k < IDS_PER_THREAD; k++)
            v[k] = __ldcg(tables + src[k]);      // 4 independent in-flight loads
        #pragma unroll
        for (int k = 0; k < IDS_PER_THREAD; k++)
            __stcs(out + (size_t)(n0 + k) * 32u + (size_t)lane, v[k]);
    } else {
        for (int k = 0; k < IDS_PER_THREAD && n0 + k < n_ids; k++) {
            uint32_t id  = (uint32_t)__ldg(ids + n0 + k);
            uint32_t idx = hash_id(id, seed);
            float4 v = __ldcg(tables + ((size_t)h * TABLE_SIZE + idx) * 8u + (size_t)j);
            __stcs(out + (size_t)(n0 + k) * 32u + (size_t)lane, v);
        }
    }
}

extern "C" void kernel_launch(void* const* d_in, const int* in_sizes, int n_in,
                              void* d_out, int out_size) {
    const int*    ids    = (const int*)d_in[0];
    const float4* tables = (const float4*)d_in[1];
    float4*       out    = (float4*)d_out;

    int n_ids = in_sizes[0];             // 819200
    // one thread per (lane, 4-id group): total = n_ids/4 * 32
    long long total = ((long long)n_ids + IDS_PER_THREAD - 1) / IDS_PER_THREAD * 32;
    int threads = 256;
    int blocks = (int)((total + threads - 1) / threads);
    bloom_embedding_kernel<<<blocks, threads>>>(ids, tables, out, n_ids);
}